// round 15
// baseline (speedup 1.0000x reference)
#include <cuda_runtime.h>
#include <cuda_bf16.h>
#include <cuda_fp16.h>
#include <cstdint>
#include <cstddef>

// ---------------------------------------------------------------------------
// MessagePassing R14:
//  - transform: 4 warps/block, each warp = 2 m16 strips x 64 cols; B fragments
//    register-reused across strips (-40% smem crossbar bytes); A split from
//    fp32 in-kernel (Xint + all prep_x launches removed); zeroing folded in.
//  - scatter/gru_pass2 as in R11/R13.
// ---------------------------------------------------------------------------

#define MAX_ATOMS 30720
#define WTAB_ROWS 2688          // 1088 bonds | 576 angles | 832 dihedrals | 192 gru
typedef uint32_t u32;

__device__ float g_h [(size_t)MAX_ATOMS * 64];
__device__ float g_a [(size_t)MAX_ATOMS * 64];
__device__ float g_b [(size_t)MAX_ATOMS * 64];
__device__ __half g_T16[(size_t)MAX_ATOMS * 1088];   // 65 MB max
__device__ float g_gi[(size_t)MAX_ATOMS * 192];
__device__ u32 g_Wint[(size_t)WTAB_ROWS * 64];       // interleaved hi/lo

// ---------------------------------------------------------------------------
__device__ __forceinline__ void mma16816(float* d, u32 a0, u32 a1, u32 a2, u32 a3,
                                         u32 b0, u32 b1) {
    asm volatile(
        "mma.sync.aligned.m16n8k16.row.col.f32.bf16.bf16.f32 "
        "{%0,%1,%2,%3}, {%4,%5,%6,%7}, {%8,%9}, {%0,%1,%2,%3};"
        : "+f"(d[0]), "+f"(d[1]), "+f"(d[2]), "+f"(d[3])
        : "r"(a0), "r"(a1), "r"(a2), "r"(a3), "r"(b0), "r"(b1));
}

__device__ __forceinline__ u32 pack_bf2(float a, float b) {
    __nv_bfloat162 t = __floats2bfloat162_rn(a, b);
    return *reinterpret_cast<u32*>(&t);
}

__device__ __forceinline__ uint2 split_pair(float a, float b) {
    float ha = __bfloat162float(__float2bfloat16(a));
    float hb = __bfloat162float(__float2bfloat16(b));
    return make_uint2(pack_bf2(a, b), pack_bf2(a - ha, b - hb));
}

// ---------------------------------------------------------------------------
__global__ void prep_weights_kernel(const float* __restrict__ We, const float* __restrict__ be,
                                    const float* __restrict__ Wa, const float* __restrict__ ba,
                                    const float* __restrict__ Wd, const float* __restrict__ bd,
                                    const float* __restrict__ wi,
                                    u32* __restrict__ Wint)
{
    int idx = blockIdx.x * 256 + threadIdx.x;
    if (idx >= WTAB_ROWS * 32) return;
    int row = idx >> 5, q = idx & 31;
    const float* src; int r;
    if      (row < 1024) { src = We; r = row; }
    else if (row < 1088) { src = be; r = row - 1024; }
    else if (row < 1600) { src = Wa; r = row - 1088; }
    else if (row < 1664) { src = ba; r = row - 1600; }
    else if (row < 2432) { src = Wd; r = row - 1664; }
    else if (row < 2496) { src = bd; r = row - 2432; }
    else                 { src = wi; r = row - 2496; }
    float2 x = *reinterpret_cast<const float2*>(src + r * 64 + q * 2);
    *reinterpret_cast<uint2*>(&Wint[(size_t)row * 64 + q * 2]) = split_pair(x.x, x.y);
}

// ---------------------------------------------------------------------------
// transform: block = 128 atoms x ONE 64-col tile, 4 warps.
// Each warp: rows [mo, mo+32), two m16 strips; B fragments reused.
// smem (interleaved, pitch 72 u32): As [128][72], Bs [64][72] = 55296 B.
// ---------------------------------------------------------------------------
#define SMEM_U32 (128 * 72 + 64 * 72)   // 13824 u32 = 55296 B

template <bool TRANS>
__global__ void __launch_bounds__(128)
transform_mma_kernel(const float* __restrict__ X,
                     const u32* __restrict__ Wint,
                     int wrow0,
                     void* __restrict__ Tout, int tpitch,
                     const float* __restrict__ bias,
                     float* __restrict__ zero_out,
                     int natoms)
{
    extern __shared__ u32 sm[];
    u32* As = sm;                  // [128][72]
    u32* Bs = As + 128 * 72;       // [64][72]

    const int tid  = threadIdx.x;
    const int a0   = blockIdx.x * 128;
    const int tile = blockIdx.y;
    const int c0   = tile * 64;

    // ---- zero next accumulator (y==0 blocks) ----
    if (zero_out != nullptr && tile == 0) {
        float4 z4 = make_float4(0.f, 0.f, 0.f, 0.f);
        float4* zo = reinterpret_cast<float4*>(zero_out);
        for (int idx = tid; idx < 128 * 16; idx += 128) {
            int v = a0 + (idx >> 4);
            if (v < natoms) zo[(size_t)v * 16 + (idx & 15)] = z4;
        }
    }

    // ---- A fill: fp32 float4 -> bf16 hi/lo interleaved uint4 ----
    {
        const float4* Xv4 = reinterpret_cast<const float4*>(X);
        for (int idx = tid; idx < 128 * 16; idx += 128) {
            int r = idx >> 4, f4 = idx & 15;
            int v = a0 + r;
            float4 x = (v < natoms) ? Xv4[(size_t)v * 16 + f4]
                                    : make_float4(0.f, 0.f, 0.f, 0.f);
            uint2 s0 = split_pair(x.x, x.y);
            uint2 s1 = split_pair(x.z, x.w);
            *reinterpret_cast<uint4*>(&As[r * 72 + f4 * 4]) =
                make_uint4(s0.x, s0.y, s1.x, s1.y);
        }
    }
    // ---- B fill: uint4 copy of interleaved weight rows ----
    {
        const uint4* Wi4 = reinterpret_cast<const uint4*>(Wint) + (size_t)(wrow0 + c0) * 16;
        for (int idx = tid; idx < 64 * 16; idx += 128) {
            int r = idx >> 4, q4 = idx & 15;
            *reinterpret_cast<uint4*>(&Bs[r * 72 + q4 * 4]) = Wi4[r * 16 + q4];
        }
    }
    __syncthreads();

    const int wid = tid >> 5, lane = tid & 31;
    const int g = lane >> 2, t = lane & 3;
    const int mo = wid * 32;

    float acc[2][8][4];
#pragma unroll
    for (int st = 0; st < 2; ++st)
#pragma unroll
        for (int nt = 0; nt < 8; ++nt) {
            acc[st][nt][0] = 0.f; acc[st][nt][1] = 0.f;
            acc[st][nt][2] = 0.f; acc[st][nt][3] = 0.f;
        }

#pragma unroll
    for (int ks = 0; ks < 4; ++ks) {
        const int kc = ks * 16 + 2 * t;        // interleaved u32 col
        // A fragments: strip0 rows mo+g, mo+g+8 ; strip1 rows mo+16+g, +8
        uint2 p0 = *reinterpret_cast<const uint2*>(&As[(mo + g)      * 72 + kc]);
        uint2 p1 = *reinterpret_cast<const uint2*>(&As[(mo + g + 8)  * 72 + kc]);
        uint2 p2 = *reinterpret_cast<const uint2*>(&As[(mo + g)      * 72 + kc + 8]);
        uint2 p3 = *reinterpret_cast<const uint2*>(&As[(mo + g + 8)  * 72 + kc + 8]);
        uint2 r0 = *reinterpret_cast<const uint2*>(&As[(mo + g + 16) * 72 + kc]);
        uint2 r1 = *reinterpret_cast<const uint2*>(&As[(mo + g + 24) * 72 + kc]);
        uint2 r2 = *reinterpret_cast<const uint2*>(&As[(mo + g + 16) * 72 + kc + 8]);
        uint2 r3 = *reinterpret_cast<const uint2*>(&As[(mo + g + 24) * 72 + kc + 8]);
#pragma unroll
        for (int nt = 0; nt < 8; ++nt) {
            const int br = nt * 8 + g;
            uint2 q0 = *reinterpret_cast<const uint2*>(&Bs[br * 72 + kc]);
            uint2 q1 = *reinterpret_cast<const uint2*>(&Bs[br * 72 + kc + 8]);
            // strip 0
            mma16816(acc[0][nt], p0.x, p1.x, p2.x, p3.x, q0.x, q1.x);  // hi*hi
            mma16816(acc[0][nt], p0.x, p1.x, p2.x, p3.x, q0.y, q1.y);  // hi*lo
            mma16816(acc[0][nt], p0.y, p1.y, p2.y, p3.y, q0.x, q1.x);  // lo*hi
            // strip 1 (B regs reused)
            mma16816(acc[1][nt], r0.x, r1.x, r2.x, r3.x, q0.x, q1.x);
            mma16816(acc[1][nt], r0.x, r1.x, r2.x, r3.x, q0.y, q1.y);
            mma16816(acc[1][nt], r0.y, r1.y, r2.y, r3.y, q0.x, q1.x);
        }
    }

    // epilogue: fragment d0=(g,2t) d1=(g,2t+1) d2=(g+8,2t) d3=(g+8,2t+1)
#pragma unroll
    for (int st = 0; st < 2; ++st) {
        const int v1 = a0 + mo + st * 16 + g;
        const int v2 = v1 + 8;
        if (TRANS) {
            float* T = reinterpret_cast<float*>(Tout);
#pragma unroll
            for (int nt = 0; nt < 8; ++nt) {
                int c = c0 + nt * 8 + 2 * t;
                float b0 = bias[c], b1 = bias[c + 1];
                if (v1 < natoms) {
                    T[(size_t)c * natoms + v1]       = acc[st][nt][0] + b0;
                    T[(size_t)(c + 1) * natoms + v1] = acc[st][nt][1] + b1;
                }
                if (v2 < natoms) {
                    T[(size_t)c * natoms + v2]       = acc[st][nt][2] + b0;
                    T[(size_t)(c + 1) * natoms + v2] = acc[st][nt][3] + b1;
                }
            }
        } else {
            __half* T = reinterpret_cast<__half*>(Tout);
#pragma unroll
            for (int nt = 0; nt < 8; ++nt) {
                int c = c0 + nt * 8 + 2 * t;
                if (v1 < natoms)
                    *reinterpret_cast<__half2*>(T + (size_t)v1 * tpitch + c) =
                        __float22half2_rn(make_float2(acc[st][nt][0], acc[st][nt][1]));
                if (v2 < natoms)
                    *reinterpret_cast<__half2*>(T + (size_t)v2 * tpitch + c) =
                        __float22half2_rn(make_float2(acc[st][nt][2], acc[st][nt][3]));
            }
        }
    }
}

// ---------------------------------------------------------------------------
// scatter: 16 lanes/edge (lane i4 -> dims 4*i4..4*i4+3), 16 edges/block.
// ---------------------------------------------------------------------------
template <int KF>
__global__ void __launch_bounds__(256)
scatter_kernel(const __half* __restrict__ T, int tpitch,
               const float* __restrict__ feat,
               const int*   __restrict__ idx,
               float*       __restrict__ out,
               int nedges)
{
    const int tid = threadIdx.x;
    const int g = tid >> 4, i4 = tid & 15;
    const int e = blockIdx.x * 16 + g;
    if (e >= nedges) return;

    const int src = __ldg(&idx[2 * e + 1]);
    const int dst = __ldg(&idx[2 * e + 0]);
    const uint2* trow =
        reinterpret_cast<const uint2*>(T + (size_t)src * tpitch) + i4;

    float f[KF];
    const float4* fp4 = reinterpret_cast<const float4*>(feat + (size_t)e * KF);
#pragma unroll
    for (int q = 0; q < KF / 4; ++q) {
        float4 ff = __ldg(&fp4[q]);
        f[4 * q] = ff.x; f[4 * q + 1] = ff.y; f[4 * q + 2] = ff.z; f[4 * q + 3] = ff.w;
    }

    uint2 bt = __ldg(&trow[KF * 16]);   // bias column group, weight 1
    float2 b01 = __half22float2(*reinterpret_cast<__half2*>(&bt.x));
    float2 b23 = __half22float2(*reinterpret_cast<__half2*>(&bt.y));
    float m0 = b01.x, m1 = b01.y, m2 = b23.x, m3 = b23.y;
#pragma unroll
    for (int kk = 0; kk < KF; ++kk) {
        uint2 tv = __ldg(&trow[kk * 16]);
        float2 t01 = __half22float2(*reinterpret_cast<__half2*>(&tv.x));
        float2 t23 = __half22float2(*reinterpret_cast<__half2*>(&tv.y));
        m0 = fmaf(f[kk], t01.x, m0);
        m1 = fmaf(f[kk], t01.y, m1);
        m2 = fmaf(f[kk], t23.x, m2);
        m3 = fmaf(f[kk], t23.y, m3);
    }

    float* o = out + (size_t)dst * 64 + 4 * i4;
    atomicAdd(o + 0, m0);
    atomicAdd(o + 1, m1);
    atomicAdd(o + 2, m2);
    atomicAdd(o + 3, m3);
}

// ---------------------------------------------------------------------------
// GRU pass2; optionally zeroes the next scatter accumulator.
// ---------------------------------------------------------------------------
__global__ void __launch_bounds__(128)
gru_pass2_kernel(const float* __restrict__ hprev,
                 const float* __restrict__ giT,
                 const float* __restrict__ wh,
                 const float* __restrict__ bh,
                 float* __restrict__ hout,
                 float* __restrict__ zero_out,
                 int natoms)
{
    __shared__ float Xs[128 * 65];
    const int tid = threadIdx.x;
    const int a0  = blockIdx.x * 128;

    for (int idx = tid; idx < 128 * 64; idx += 128) {
        int r = idx >> 6, j = idx & 63;
        int v = a0 + r;
        Xs[r * 65 + j] = (v < natoms) ? hprev[(size_t)v * 64 + j] : 0.f;
    }
    __syncthreads();

    float x[64];
#pragma unroll
    for (int j = 0; j < 64; ++j) x[j] = Xs[tid * 65 + j];

    const int v  = a0 + tid;
    const int vv = (v < natoms) ? v : 0;

    for (int i = 0; i < 64; ++i) {
        float ar = bh[i], az = bh[64 + i], an = bh[128 + i];
        const float4* wr = reinterpret_cast<const float4*>(wh + (size_t)i * 64);
        const float4* wz = reinterpret_cast<const float4*>(wh + (size_t)(64 + i) * 64);
        const float4* wn = reinterpret_cast<const float4*>(wh + (size_t)(128 + i) * 64);
#pragma unroll
        for (int j4 = 0; j4 < 16; ++j4) {
            float4 a4 = wr[j4], b4 = wz[j4], c4 = wn[j4];
            ar = fmaf(x[4*j4+0], a4.x, ar); ar = fmaf(x[4*j4+1], a4.y, ar);
            ar = fmaf(x[4*j4+2], a4.z, ar); ar = fmaf(x[4*j4+3], a4.w, ar);
            az = fmaf(x[4*j4+0], b4.x, az); az = fmaf(x[4*j4+1], b4.y, az);
            az = fmaf(x[4*j4+2], b4.z, az); az = fmaf(x[4*j4+3], b4.w, az);
            an = fmaf(x[4*j4+0], c4.x, an); an = fmaf(x[4*j4+1], c4.y, an);
            an = fmaf(x[4*j4+2], c4.z, an); an = fmaf(x[4*j4+3], c4.w, an);
        }
        float gir = giT[(size_t)i         * natoms + vv];
        float giz = giT[(size_t)(64 + i)  * natoms + vv];
        float gin = giT[(size_t)(128 + i) * natoms + vv];

        float r_ = 1.f / (1.f + __expf(-(gir + ar)));
        float z_ = 1.f / (1.f + __expf(-(giz + az)));
        float n_ = tanhf(gin + r_ * an);
        Xs[tid * 65 + i] = (1.f - z_) * n_ + z_ * x[i];
    }
    __syncthreads();

    for (int idx = tid; idx < 128 * 64; idx += 128) {
        int r = idx >> 6, j = idx & 63;
        int v2 = a0 + r;
        if (v2 < natoms) {
            hout[(size_t)v2 * 64 + j] = Xs[r * 65 + j];
            if (zero_out) zero_out[(size_t)v2 * 64 + j] = 0.f;
        }
    }
}

// ---------------------------------------------------------------------------
extern "C" void kernel_launch(void* const* d_in, const int* in_sizes, int n_in,
                              void* d_out, int out_size)
{
    const float* atom  = (const float*)d_in[0];
    const float* bf    = (const float*)d_in[1];
    const int*   bidx  = (const int*)  d_in[2];
    const float* anf   = (const float*)d_in[3];
    const int*   anidx = (const int*)  d_in[4];
    const float* dif   = (const float*)d_in[5];
    const int*   diidx = (const int*)  d_in[6];
    const float* We    = (const float*)d_in[7];
    const float* be    = (const float*)d_in[8];
    const float* Wa    = (const float*)d_in[9];
    const float* ba    = (const float*)d_in[10];
    const float* Wd    = (const float*)d_in[11];
    const float* bd    = (const float*)d_in[12];
    const float* wi    = (const float*)d_in[13];
    const float* wh    = (const float*)d_in[14];
    const float* bi    = (const float*)d_in[15];
    const float* bh    = (const float*)d_in[16];
    float* out = (float*)d_out;

    const int natoms = in_sizes[0] / 64;
    const int nb = in_sizes[2] / 2;
    const int na = in_sizes[4] / 2;
    const int nd = in_sizes[6] / 2;

    float *pH, *pA, *pB, *pGI;
    __half* pT;
    u32 *pWint;
    cudaGetSymbolAddress((void**)&pH,    g_h);
    cudaGetSymbolAddress((void**)&pA,    g_a);
    cudaGetSymbolAddress((void**)&pB,    g_b);
    cudaGetSymbolAddress((void**)&pT,    g_T16);
    cudaGetSymbolAddress((void**)&pGI,   g_gi);
    cudaGetSymbolAddress((void**)&pWint, g_Wint);

    cudaFuncSetAttribute(transform_mma_kernel<false>,
                         cudaFuncAttributeMaxDynamicSharedMemorySize, SMEM_U32 * 4);
    cudaFuncSetAttribute(transform_mma_kernel<true>,
                         cudaFuncAttributeMaxDynamicSharedMemorySize, SMEM_U32 * 4);

    const int abk = (natoms + 127) / 128;

    prep_weights_kernel<<<(WTAB_ROWS * 32 + 255) / 256, 256>>>(
        We, be, Wa, ba, Wd, bd, wi, pWint);

    for (int s = 0; s < 4; ++s) {
        const float* hx = (s == 0) ? atom : pH;

        // ---- bonds: 17 tiles (weight rows 0..1087); accumulate into pA ----
        transform_mma_kernel<false><<<dim3(abk, 17), 128, SMEM_U32 * 4>>>(
            hx, pWint, 0, pT, 1088, nullptr,
            (s == 0) ? pA : nullptr,           // s>0: gru_pass2 zeroed pA
            natoms);
        scatter_kernel<16><<<(nb + 15) / 16, 256>>>(pT, 1088, bf, bidx, pA, nb);

        // ---- angles: 9 tiles (rows 1088..1663); accumulate into pB ----
        transform_mma_kernel<false><<<dim3(abk, 9), 128, SMEM_U32 * 4>>>(
            pA, pWint, 1088, pT, 576, nullptr, pB, natoms);
        scatter_kernel<8><<<(na + 15) / 16, 256>>>(pT, 576, anf, anidx, pB, na);

        // ---- dihedrals: 13 tiles (rows 1664..2495); accumulate into pA ----
        transform_mma_kernel<false><<<dim3(abk, 13), 128, SMEM_U32 * 4>>>(
            pB, pWint, 1664, pT, 832, nullptr, pA, natoms);
        scatter_kernel<12><<<(nd + 15) / 16, 256>>>(pT, 832, dif, diidx, pA, nd);

        // ---- GRU pass1: 3 tiles (rows 2496..2687), fp32 transposed + bi ----
        transform_mma_kernel<true><<<dim3(abk, 3), 128, SMEM_U32 * 4>>>(
            pA, pWint, 2496, pGI, 0, bi, nullptr, natoms);
        const bool last = (s == 3);
        gru_pass2_kernel<<<abk, 128>>>(
            hx, pGI, wh, bh,
            last ? out : pH,
            last ? nullptr : pA,
            natoms);
    }
}

// round 16
// speedup vs baseline: 1.6142x; 1.6142x over previous
#include <cuda_runtime.h>
#include <cuda_bf16.h>
#include <cuda_fp16.h>
#include <cstdint>
#include <cstddef>

// ---------------------------------------------------------------------------
// MessagePassing R15: R11 pipeline (best, 1602us) with the GRU's gh GEMM moved
// from scalar FFMA onto the MMA transform (wh rows appended to weight table),
// plus a light elementwise gate kernel (fuses h-split + accumulator zeroing).
// Transform kernel is VERBATIM R11 (256 thr, 1 tile/block — R10/R12/R14
// variants all regressed: multi-tile hurts occupancy, 2-strip blows regs).
// ---------------------------------------------------------------------------

#define MAX_ATOMS 30720
#define WTAB_ROWS 2880     // 1088 bonds | 576 angles | 832 dihedrals | 192 wi | 192 wh
typedef uint32_t u32;

__device__ float g_h [(size_t)MAX_ATOMS * 64];
__device__ float g_a [(size_t)MAX_ATOMS * 64];
__device__ float g_b [(size_t)MAX_ATOMS * 64];
__device__ __half g_T16[(size_t)MAX_ATOMS * 1088];   // 65 MB max
__device__ float g_gi[(size_t)MAX_ATOMS * 192];      // giT [192][N]
__device__ float g_gh[(size_t)MAX_ATOMS * 192];      // ghT [192][N]
__device__ u32 g_Wint [(size_t)WTAB_ROWS * 64];      // interleaved hi/lo
__device__ u32 g_Xint [(size_t)MAX_ATOMS * 64];      // split of message vec
__device__ u32 g_XintH[(size_t)MAX_ATOMS * 64];      // split of h

// ---------------------------------------------------------------------------
__device__ __forceinline__ void mma16816(float* d, u32 a0, u32 a1, u32 a2, u32 a3,
                                         u32 b0, u32 b1) {
    asm volatile(
        "mma.sync.aligned.m16n8k16.row.col.f32.bf16.bf16.f32 "
        "{%0,%1,%2,%3}, {%4,%5,%6,%7}, {%8,%9}, {%0,%1,%2,%3};"
        : "+f"(d[0]), "+f"(d[1]), "+f"(d[2]), "+f"(d[3])
        : "r"(a0), "r"(a1), "r"(a2), "r"(a3), "r"(b0), "r"(b1));
}

__device__ __forceinline__ u32 pack_bf2(float a, float b) {
    __nv_bfloat162 t = __floats2bfloat162_rn(a, b);
    return *reinterpret_cast<u32*>(&t);
}

__device__ __forceinline__ uint2 split_pair(float a, float b) {
    float ha = __bfloat162float(__float2bfloat16(a));
    float hb = __bfloat162float(__float2bfloat16(b));
    return make_uint2(pack_bf2(a, b), pack_bf2(a - ha, b - hb));
}

// ---------------------------------------------------------------------------
__global__ void prep_weights_kernel(const float* __restrict__ We, const float* __restrict__ be,
                                    const float* __restrict__ Wa, const float* __restrict__ ba,
                                    const float* __restrict__ Wd, const float* __restrict__ bd,
                                    const float* __restrict__ wi, const float* __restrict__ wh,
                                    u32* __restrict__ Wint)
{
    int idx = blockIdx.x * 256 + threadIdx.x;
    if (idx >= WTAB_ROWS * 32) return;
    int row = idx >> 5, q = idx & 31;
    const float* src; int r;
    if      (row < 1024) { src = We; r = row; }
    else if (row < 1088) { src = be; r = row - 1024; }
    else if (row < 1600) { src = Wa; r = row - 1088; }
    else if (row < 1664) { src = ba; r = row - 1600; }
    else if (row < 2432) { src = Wd; r = row - 1664; }
    else if (row < 2496) { src = bd; r = row - 2432; }
    else if (row < 2688) { src = wi; r = row - 2496; }
    else                 { src = wh; r = row - 2688; }
    float2 x = *reinterpret_cast<const float2*>(src + r * 64 + q * 2);
    *reinterpret_cast<uint2*>(&Wint[(size_t)row * 64 + q * 2]) = split_pair(x.x, x.y);
}

// ---------------------------------------------------------------------------
__global__ void prep_x_kernel(const float* __restrict__ X,
                              u32* __restrict__ Xint,
                              float* __restrict__ zero_out, int natoms)
{
    int idx = blockIdx.x * 256 + threadIdx.x;
    if (idx >= natoms * 32) return;
    int v = idx >> 5, q = idx & 31;
    float2 x = *reinterpret_cast<const float2*>(X + (size_t)v * 64 + q * 2);
    *reinterpret_cast<uint2*>(&Xint[(size_t)v * 64 + q * 2]) = split_pair(x.x, x.y);
    if (zero_out)
        *reinterpret_cast<float2*>(zero_out + (size_t)v * 64 + q * 2) =
            make_float2(0.f, 0.f);
}

// ---------------------------------------------------------------------------
// transform (VERBATIM R11): block = 128 atoms x ONE 64-col tile, 8 warps.
// smem (interleaved, pitch 72 u32): As [128][72], Bs [64][72] = 55296 B.
// ---------------------------------------------------------------------------
#define SMEM_U32 (128 * 72 + 64 * 72)   // 13824 u32 = 55296 B

template <bool TRANS>
__global__ void __launch_bounds__(256)
transform_mma_kernel(const u32* __restrict__ Xint,
                     const u32* __restrict__ Wint,
                     int wrow0,
                     void* __restrict__ Tout, int tpitch,
                     const float* __restrict__ bias,
                     int natoms)
{
    extern __shared__ u32 sm[];
    u32* As = sm;                  // [128][72]
    u32* Bs = As + 128 * 72;       // [64][72]

    const int tid  = threadIdx.x;
    const int a0   = blockIdx.x * 128;
    const int tile = blockIdx.y;
    const int c0   = tile * 64;

    {
        const uint4* Xi4 = reinterpret_cast<const uint4*>(Xint);
        const uint4 z4 = make_uint4(0, 0, 0, 0);
        for (int idx = tid; idx < 128 * 16; idx += 256) {
            int r = idx >> 4, q4 = idx & 15;
            int v = a0 + r;
            uint4 val = (v < natoms) ? Xi4[(size_t)v * 16 + q4] : z4;
            *reinterpret_cast<uint4*>(&As[r * 72 + q4 * 4]) = val;
        }
    }
    {
        const uint4* Wi4 = reinterpret_cast<const uint4*>(Wint) + (size_t)(wrow0 + c0) * 16;
        for (int idx = tid; idx < 64 * 16; idx += 256) {
            int r = idx >> 4, q4 = idx & 15;
            *reinterpret_cast<uint4*>(&Bs[r * 72 + q4 * 4]) = Wi4[r * 16 + q4];
        }
    }
    __syncthreads();

    const int wid = tid >> 5, lane = tid & 31;
    const int g = lane >> 2, t = lane & 3;
    const int mo = wid * 16;
    const int v1 = a0 + mo + g, v2 = v1 + 8;

    float acc[8][4];
#pragma unroll
    for (int nt = 0; nt < 8; ++nt) {
        acc[nt][0] = 0.f; acc[nt][1] = 0.f; acc[nt][2] = 0.f; acc[nt][3] = 0.f;
    }

#pragma unroll
    for (int ks = 0; ks < 4; ++ks) {
        const int kc = ks * 16 + 2 * t;
        uint2 p0 = *reinterpret_cast<const uint2*>(&As[(mo + g)     * 72 + kc]);
        uint2 p1 = *reinterpret_cast<const uint2*>(&As[(mo + g + 8) * 72 + kc]);
        uint2 p2 = *reinterpret_cast<const uint2*>(&As[(mo + g)     * 72 + kc + 8]);
        uint2 p3 = *reinterpret_cast<const uint2*>(&As[(mo + g + 8) * 72 + kc + 8]);
#pragma unroll
        for (int nt = 0; nt < 8; ++nt) {
            const int br = nt * 8 + g;
            uint2 q0 = *reinterpret_cast<const uint2*>(&Bs[br * 72 + kc]);
            uint2 q1 = *reinterpret_cast<const uint2*>(&Bs[br * 72 + kc + 8]);
            mma16816(acc[nt], p0.x, p1.x, p2.x, p3.x, q0.x, q1.x);  // hi*hi
            mma16816(acc[nt], p0.x, p1.x, p2.x, p3.x, q0.y, q1.y);  // hi*lo
            mma16816(acc[nt], p0.y, p1.y, p2.y, p3.y, q0.x, q1.x);  // lo*hi
        }
    }

    if (TRANS) {
        float* T = reinterpret_cast<float*>(Tout);
#pragma unroll
        for (int nt = 0; nt < 8; ++nt) {
            int c = c0 + nt * 8 + 2 * t;
            float b0 = bias[c], b1 = bias[c + 1];
            if (v1 < natoms) {
                T[(size_t)c * natoms + v1]       = acc[nt][0] + b0;
                T[(size_t)(c + 1) * natoms + v1] = acc[nt][1] + b1;
            }
            if (v2 < natoms) {
                T[(size_t)c * natoms + v2]       = acc[nt][2] + b0;
                T[(size_t)(c + 1) * natoms + v2] = acc[nt][3] + b1;
            }
        }
    } else {
        __half* T = reinterpret_cast<__half*>(Tout);
#pragma unroll
        for (int nt = 0; nt < 8; ++nt) {
            int c = c0 + nt * 8 + 2 * t;
            if (v1 < natoms)
                *reinterpret_cast<__half2*>(T + (size_t)v1 * tpitch + c) =
                    __float22half2_rn(make_float2(acc[nt][0], acc[nt][1]));
            if (v2 < natoms)
                *reinterpret_cast<__half2*>(T + (size_t)v2 * tpitch + c) =
                    __float22half2_rn(make_float2(acc[nt][2], acc[nt][3]));
        }
    }
}

// ---------------------------------------------------------------------------
// scatter (VERBATIM R11): 16 lanes/edge, 16 edges/block.
// ---------------------------------------------------------------------------
template <int KF>
__global__ void __launch_bounds__(256)
scatter_kernel(const __half* __restrict__ T, int tpitch,
               const float* __restrict__ feat,
               const int*   __restrict__ idx,
               float*       __restrict__ out,
               int nedges)
{
    const int tid = threadIdx.x;
    const int g = tid >> 4, i4 = tid & 15;
    const int e = blockIdx.x * 16 + g;
    if (e >= nedges) return;

    const int src = __ldg(&idx[2 * e + 1]);
    const int dst = __ldg(&idx[2 * e + 0]);
    const uint2* trow =
        reinterpret_cast<const uint2*>(T + (size_t)src * tpitch) + i4;

    float f[KF];
    const float4* fp4 = reinterpret_cast<const float4*>(feat + (size_t)e * KF);
#pragma unroll
    for (int q = 0; q < KF / 4; ++q) {
        float4 ff = __ldg(&fp4[q]);
        f[4 * q] = ff.x; f[4 * q + 1] = ff.y; f[4 * q + 2] = ff.z; f[4 * q + 3] = ff.w;
    }

    uint2 bt = __ldg(&trow[KF * 16]);
    float2 b01 = __half22float2(*reinterpret_cast<__half2*>(&bt.x));
    float2 b23 = __half22float2(*reinterpret_cast<__half2*>(&bt.y));
    float m0 = b01.x, m1 = b01.y, m2 = b23.x, m3 = b23.y;
#pragma unroll
    for (int kk = 0; kk < KF; ++kk) {
        uint2 tv = __ldg(&trow[kk * 16]);
        float2 t01 = __half22float2(*reinterpret_cast<__half2*>(&tv.x));
        float2 t23 = __half22float2(*reinterpret_cast<__half2*>(&tv.y));
        m0 = fmaf(f[kk], t01.x, m0);
        m1 = fmaf(f[kk], t01.y, m1);
        m2 = fmaf(f[kk], t23.x, m2);
        m3 = fmaf(f[kk], t23.y, m3);
    }

    float* o = out + (size_t)dst * 64 + 4 * i4;
    atomicAdd(o + 0, m0);
    atomicAdd(o + 1, m1);
    atomicAdd(o + 2, m2);
    atomicAdd(o + 3, m3);
}

// ---------------------------------------------------------------------------
// gate kernel: h' = (1-z)n + z h from precomputed giT/ghT (bias included).
// Fuses: split(h') -> XintH (for next bonds + next gh), zero next accumulator.
// ---------------------------------------------------------------------------
__global__ void __launch_bounds__(128)
gru_gate_kernel(const float* __restrict__ hprev,
                const float* __restrict__ giT,   // [192][N], includes bi
                const float* __restrict__ ghT,   // [192][N], includes bh
                float* __restrict__ hout,
                u32* __restrict__ xint_out,
                float* __restrict__ zero_out,
                int natoms)
{
    __shared__ float Xs[128 * 65];
    const int tid = threadIdx.x;
    const int a0  = blockIdx.x * 128;

    // coalesced h tile load
    for (int idx = tid; idx < 128 * 64; idx += 128) {
        int r = idx >> 6, j = idx & 63;
        int v = a0 + r;
        Xs[r * 65 + j] = (v < natoms) ? hprev[(size_t)v * 64 + j] : 0.f;
    }
    __syncthreads();

    const int v  = a0 + tid;
    const int vv = (v < natoms) ? v : 0;

#pragma unroll 4
    for (int i = 0; i < 64; ++i) {
        float gir = giT[(size_t)i         * natoms + vv];
        float giz = giT[(size_t)(64 + i)  * natoms + vv];
        float gin = giT[(size_t)(128 + i) * natoms + vv];
        float ghr = ghT[(size_t)i         * natoms + vv];
        float ghz = ghT[(size_t)(64 + i)  * natoms + vv];
        float ghn = ghT[(size_t)(128 + i) * natoms + vv];

        float r_ = 1.f / (1.f + __expf(-(gir + ghr)));
        float z_ = 1.f / (1.f + __expf(-(giz + ghz)));
        float n_ = tanhf(gin + r_ * ghn);
        Xs[tid * 65 + i] = (1.f - z_) * n_ + z_ * Xs[tid * 65 + i];
    }
    __syncthreads();

    for (int idx = tid; idx < 128 * 64; idx += 128) {
        int r = idx >> 6, j = idx & 63;
        int v2 = a0 + r;
        if (v2 < natoms) hout[(size_t)v2 * 64 + j] = Xs[r * 65 + j];
    }
    if (xint_out) {
        for (int idx = tid; idx < 128 * 32; idx += 128) {
            int r = idx >> 5, q = idx & 31;
            int v2 = a0 + r;
            if (v2 < natoms) {
                float a = Xs[r * 65 + 2 * q], b = Xs[r * 65 + 2 * q + 1];
                *reinterpret_cast<uint2*>(&xint_out[(size_t)v2 * 64 + q * 2]) =
                    split_pair(a, b);
                *reinterpret_cast<float2*>(zero_out + (size_t)v2 * 64 + q * 2) =
                    make_float2(0.f, 0.f);
            }
        }
    }
}

// ---------------------------------------------------------------------------
extern "C" void kernel_launch(void* const* d_in, const int* in_sizes, int n_in,
                              void* d_out, int out_size)
{
    const float* atom  = (const float*)d_in[0];
    const float* bf    = (const float*)d_in[1];
    const int*   bidx  = (const int*)  d_in[2];
    const float* anf   = (const float*)d_in[3];
    const int*   anidx = (const int*)  d_in[4];
    const float* dif   = (const float*)d_in[5];
    const int*   diidx = (const int*)  d_in[6];
    const float* We    = (const float*)d_in[7];
    const float* be    = (const float*)d_in[8];
    const float* Wa    = (const float*)d_in[9];
    const float* ba    = (const float*)d_in[10];
    const float* Wd    = (const float*)d_in[11];
    const float* bd    = (const float*)d_in[12];
    const float* wi    = (const float*)d_in[13];
    const float* wh    = (const float*)d_in[14];
    const float* bi    = (const float*)d_in[15];
    const float* bh    = (const float*)d_in[16];
    float* out = (float*)d_out;

    const int natoms = in_sizes[0] / 64;
    const int nb = in_sizes[2] / 2;
    const int na = in_sizes[4] / 2;
    const int nd = in_sizes[6] / 2;

    float *pH, *pA, *pB, *pGI, *pGH;
    __half* pT;
    u32 *pWint, *pXint, *pXintH;
    cudaGetSymbolAddress((void**)&pH,     g_h);
    cudaGetSymbolAddress((void**)&pA,     g_a);
    cudaGetSymbolAddress((void**)&pB,     g_b);
    cudaGetSymbolAddress((void**)&pT,     g_T16);
    cudaGetSymbolAddress((void**)&pGI,    g_gi);
    cudaGetSymbolAddress((void**)&pGH,    g_gh);
    cudaGetSymbolAddress((void**)&pWint,  g_Wint);
    cudaGetSymbolAddress((void**)&pXint,  g_Xint);
    cudaGetSymbolAddress((void**)&pXintH, g_XintH);

    cudaFuncSetAttribute(transform_mma_kernel<false>,
                         cudaFuncAttributeMaxDynamicSharedMemorySize, SMEM_U32 * 4);
    cudaFuncSetAttribute(transform_mma_kernel<true>,
                         cudaFuncAttributeMaxDynamicSharedMemorySize, SMEM_U32 * 4);

    const int abk = (natoms + 127) / 128;
    const int xg  = (natoms * 32 + 255) / 256;

    prep_weights_kernel<<<(WTAB_ROWS * 32 + 255) / 256, 256>>>(
        We, be, Wa, ba, Wd, bd, wi, wh, pWint);
    // split(atom) -> XintH, zero bonds accumulator
    prep_x_kernel<<<xg, 256>>>(atom, pXintH, pA, natoms);

    for (int s = 0; s < 4; ++s) {
        const float* hx = (s == 0) ? atom : pH;

        // ---- bonds: 17 tiles (rows 0..1087), X = split(h); accumulate pA ----
        transform_mma_kernel<false><<<dim3(abk, 17), 256, SMEM_U32 * 4>>>(
            pXintH, pWint, 0, pT, 1088, nullptr, natoms);
        scatter_kernel<16><<<(nb + 15) / 16, 256>>>(pT, 1088, bf, bidx, pA, nb);

        // ---- angles: 9 tiles (rows 1088..1663); accumulate pB ----
        prep_x_kernel<<<xg, 256>>>(pA, pXint, pB, natoms);
        transform_mma_kernel<false><<<dim3(abk, 9), 256, SMEM_U32 * 4>>>(
            pXint, pWint, 1088, pT, 576, nullptr, natoms);
        scatter_kernel<8><<<(na + 15) / 16, 256>>>(pT, 576, anf, anidx, pB, na);

        // ---- dihedrals: 13 tiles (rows 1664..2495); accumulate pA ----
        prep_x_kernel<<<xg, 256>>>(pB, pXint, pA, natoms);
        transform_mma_kernel<false><<<dim3(abk, 13), 256, SMEM_U32 * 4>>>(
            pXint, pWint, 1664, pT, 832, nullptr, natoms);
        scatter_kernel<12><<<(nd + 15) / 16, 256>>>(pT, 832, dif, diidx, pA, nd);

        // ---- GRU: gi = a@wi^T+bi ; gh = h@wh^T+bh ; gates ----
        prep_x_kernel<<<xg, 256>>>(pA, pXint, nullptr, natoms);
        transform_mma_kernel<true><<<dim3(abk, 3), 256, SMEM_U32 * 4>>>(
            pXint, pWint, 2496, pGI, 0, bi, natoms);
        transform_mma_kernel<true><<<dim3(abk, 3), 256, SMEM_U32 * 4>>>(
            pXintH, pWint, 2688, pGH, 0, bh, natoms);
        const bool last = (s == 3);
        gru_gate_kernel<<<abk, 128>>>(
            hx, pGI, pGH,
            last ? out : pH,
            last ? nullptr : pXintH,   // split(h') for next bonds + next gh
            last ? nullptr : pA,       // zero next bonds accumulator
            natoms);
    }
}